// round 15
// baseline (speedup 1.0000x reference)
#include <cuda_runtime.h>
#include <math.h>

// Problem constants
#define BB   32
#define LL   2048
#define DIN  64
#define NC   32
#define DC   16
#define OUTD 512           // NC*DC
#define EPSQ 1e-7f

#define K1_CHUNKS 16
#define K3_CHUNKS 8        // blocks per batch in routing pass (256 l's each)
#define K3_WARPS  4
#define K3_LPW    64       // l's per warp

// Scratch (static device allocations only — no cudaMalloc allowed)
__device__ float g_colsum_part[BB][K1_CHUNKS][DIN];
__device__ float g_s_part[BB][K3_CHUNKS][NC][DIN];   // 2 MB
__device__ float g_v[BB][NC][DIN];

// ---------------------------------------------------------------------------
// K1: column sums  colsum_part[b][chunk][i] = sum over 128 l's of u[b,l,i]
// grid (K1_CHUNKS, BB), 256 threads   (exact R7 form)
// ---------------------------------------------------------------------------
__global__ void k1_colsum(const float* __restrict__ u) {
    const int b = blockIdx.y, chunk = blockIdx.x;
    const int tid = threadIdx.x;
    const int col4 = tid & 15;
    const int g    = tid >> 4;

    const float4* up = (const float4*)(u + ((size_t)b * LL + (size_t)chunk * 128) * DIN);
    float4 acc = make_float4(0.f, 0.f, 0.f, 0.f);
    #pragma unroll
    for (int r = 0; r < 8; r++) {
        float4 x = up[(size_t)(g + r * 16) * 16 + col4];
        acc.x += x.x; acc.y += x.y; acc.z += x.z; acc.w += x.w;
    }
    __shared__ __align__(16) float4 red[16][16];
    red[g][col4] = acc;
    __syncthreads();
    if (tid < 16) {
        float4 s = red[0][tid];
        #pragma unroll
        for (int i = 1; i < 16; i++) {
            float4 x = red[i][tid];
            s.x += x.x; s.y += x.y; s.z += x.z; s.w += x.w;
        }
        ((float4*)g_colsum_part[b][chunk])[tid] = s;
    }
}

// ---------------------------------------------------------------------------
// K2: per-(b,n) epilogue. grid (NC, BB), 64 threads.
// Phase 2 restructured: 64 threads compute raw[d] in 4 parallel i-quarters
// (16-deep chains), combined via shfl + smem (fixed order, deterministic).
// ---------------------------------------------------------------------------
__global__ void __launch_bounds__(64, 16) k2_update(const float* __restrict__ W,
                                                    float* __restrict__ out_final,
                                                    int mode) {
    const int n = blockIdx.x, b = blockIdx.y;
    const int t = threadIdx.x;        // 0..63 == element index i (phase 1/3)
    const int lane = t & 31;
    const int wid2 = t >> 5;          // 0..1

    __shared__ float s_sm[DIN];
    __shared__ float part[2][DC];
    __shared__ float out_sm[DC];

    // phase 1: partial-sum sweep, thread t owns element i = t
    float a = 0.f;
    if (mode == 0) {
        #pragma unroll
        for (int c = 0; c < K1_CHUNKS; c++)
            a += g_colsum_part[b][c][t];
        a *= (1.0f / 32.0f);
    } else {
        #pragma unroll
        for (int c = 0; c < K3_CHUNKS; c++)
            a += g_s_part[b][c][n][t];
    }
    s_sm[t] = a;
    __syncthreads();

    // phase 2: raw[d] = sum_i s[i]*W[i*512+n*16+d], 4-way parallel over i
    {
        const int d = lane & 15;
        const int q = (wid2 << 1) | (lane >> 4);   // quarter 0..3
        const int i0 = q * 16;
        const float* Wc = W + (size_t)n * DC + d;
        float p = 0.f;
        #pragma unroll
        for (int i = 0; i < 16; i++)
            p = fmaf(s_sm[i0 + i], Wc[(size_t)(i0 + i) * OUTD], p);
        // combine the two quarters within this warp (lanes d <-> d+16)
        p += __shfl_xor_sync(0xffffffffu, p, 16);
        if (lane < DC) part[wid2][lane] = p;       // quarter-pair partial
    }
    __syncthreads();

    // warp 0: final combine + squash
    if (wid2 == 0) {
        const int d = lane & 15;
        float raw = part[0][d] + part[1][d];       // all 32 lanes (dup over d)
        float s2 = raw * raw;
        #pragma unroll
        for (int off = 8; off; off >>= 1)
            s2 += __shfl_xor_sync(0xffffffffu, s2, off, 16);
        float o = raw * rsqrtf(s2 + EPSQ);
        if (lane < DC) {
            if (mode == 2) out_final[(size_t)b * OUTD + (size_t)n * DC + lane] = o;
            else           out_sm[lane] = o;
        }
    }

    if (mode != 2) {
        __syncthreads();
        // phase 3: v[n][i] for i = t
        const float* Wr = W + (size_t)t * OUTD + (size_t)n * DC;
        float v = 0.f;
        #pragma unroll
        for (int d = 0; d < DC; d++)
            v = fmaf(Wr[d], out_sm[d], v);
        g_v[b][n][t] = v;
    }
}

// ---------------------------------------------------------------------------
// K3: fused routing pass (exact R7 proven form), 2 l's per iteration.
// Per (b,l): logits[n] = u[l,:].v[n,:]; c = softmax_n; s[n,:] += c*u[l,:]
// grid (K3_CHUNKS, BB), 128 threads (4 warps).
// ---------------------------------------------------------------------------
__global__ void __launch_bounds__(128, 1) k3_route(const float* __restrict__ u) {
    const int b = blockIdx.y, chunk = blockIdx.x;
    const int w = threadIdx.x >> 5;
    const int lane = threadIdx.x & 31;       // lane == capsule index n

    __shared__ __align__(16) float u_buf[K3_WARPS][2][64];
    __shared__ __align__(16) float s_blk[K3_WARPS][NC][65];   // padded

    float4 v4[16];
    const float4* vp = (const float4*)(&g_v[b][lane][0]);
    #pragma unroll
    for (int k = 0; k < 16; k++) v4[k] = vp[k];

    float4 s4[16];
    #pragma unroll
    for (int k = 0; k < 16; k++) s4[k] = make_float4(0.f, 0.f, 0.f, 0.f);

    const int l0 = chunk * (K3_WARPS * K3_LPW) + w * K3_LPW;
    const float* ub = u + ((size_t)b * LL + l0) * DIN;

    for (int j = 0; j < K3_LPW; j += 2) {
        float2 ra = ((const float2*)(ub + (size_t)j * DIN))[lane];
        float2 rb = ((const float2*)(ub + (size_t)(j + 1) * DIN))[lane];
        __syncwarp();                         // WAR vs previous iteration's reads
        ((float2*)u_buf[w][0])[lane] = ra;
        ((float2*)u_buf[w][1])[lane] = rb;
        __syncwarp();
        const float4* uA = (const float4*)u_buf[w][0];
        const float4* uB = (const float4*)u_buf[w][1];

        float lA0 = 0.f, lA1 = 0.f, lB0 = 0.f, lB1 = 0.f;
        #pragma unroll
        for (int k = 0; k < 16; k += 2) {
            float4 xA = uA[k], yA = uA[k + 1];
            float4 xB = uB[k], yB = uB[k + 1];
            lA0 = fmaf(xA.x, v4[k].x, lA0);     lA0 = fmaf(xA.y, v4[k].y, lA0);
            lA0 = fmaf(xA.z, v4[k].z, lA0);     lA0 = fmaf(xA.w, v4[k].w, lA0);
            lA1 = fmaf(yA.x, v4[k + 1].x, lA1); lA1 = fmaf(yA.y, v4[k + 1].y, lA1);
            lA1 = fmaf(yA.z, v4[k + 1].z, lA1); lA1 = fmaf(yA.w, v4[k + 1].w, lA1);
            lB0 = fmaf(xB.x, v4[k].x, lB0);     lB0 = fmaf(xB.y, v4[k].y, lB0);
            lB0 = fmaf(xB.z, v4[k].z, lB0);     lB0 = fmaf(xB.w, v4[k].w, lB0);
            lB1 = fmaf(yB.x, v4[k + 1].x, lB1); lB1 = fmaf(yB.y, v4[k + 1].y, lB1);
            lB1 = fmaf(yB.z, v4[k + 1].z, lB1); lB1 = fmaf(yB.w, v4[k + 1].w, lB1);
        }
        float eA = __expf(lA0 + lA1);
        float eB = __expf(lB0 + lB1);
        float sA = eA, sB = eB;
        #pragma unroll
        for (int off = 16; off; off >>= 1) {
            sA += __shfl_xor_sync(0xffffffffu, sA, off);
            sB += __shfl_xor_sync(0xffffffffu, sB, off);
        }
        float cA = __fdividef(eA, sA);
        float cB = __fdividef(eB, sB);

        #pragma unroll
        for (int k = 0; k < 16; k++) {
            float4 xA = uA[k], xB = uB[k];
            s4[k].x = fmaf(cA, xA.x, fmaf(cB, xB.x, s4[k].x));
            s4[k].y = fmaf(cA, xA.y, fmaf(cB, xB.y, s4[k].y));
            s4[k].z = fmaf(cA, xA.z, fmaf(cB, xB.z, s4[k].z));
            s4[k].w = fmaf(cA, xA.w, fmaf(cB, xB.w, s4[k].w));
        }
    }

    #pragma unroll
    for (int k = 0; k < 16; k++) {
        s_blk[w][lane][4 * k + 0] = s4[k].x;
        s_blk[w][lane][4 * k + 1] = s4[k].y;
        s_blk[w][lane][4 * k + 2] = s4[k].z;
        s_blk[w][lane][4 * k + 3] = s4[k].w;
    }
    __syncthreads();

    float* outp = (float*)g_s_part[b][chunk];
    for (int e = threadIdx.x; e < NC * DIN; e += 128) {
        int n = e >> 6, i = e & 63;
        outp[e] = s_blk[0][n][i] + s_blk[1][n][i] + s_blk[2][n][i] + s_blk[3][n][i];
    }
}

// ---------------------------------------------------------------------------
extern "C" void kernel_launch(void* const* d_in, const int* in_sizes, int n_in,
                              void* d_out, int out_size) {
    const float* u = (const float*)d_in[0];   // [32, 2048, 64]
    const float* W = (const float*)d_in[1];   // [1, 64, 512]
    float* out = (float*)d_out;               // [32, 32, 16]

    // iteration 0: uniform c -> colsum path
    k1_colsum<<<dim3(K1_CHUNKS, BB), 256>>>(u);
    k2_update<<<dim3(NC, BB), 64>>>(W, out, 0);   // outputs0 + v0
    // iteration 1
    k3_route<<<dim3(K3_CHUNKS, BB), 128>>>(u);
    k2_update<<<dim3(NC, BB), 64>>>(W, out, 1);   // outputs1 + v1
    // iteration 2 (final)
    k3_route<<<dim3(K3_CHUNKS, BB), 128>>>(u);
    k2_update<<<dim3(NC, BB), 64>>>(W, out, 2);   // outputs2 -> d_out
}

// round 16
// speedup vs baseline: 1.0504x; 1.0504x over previous
#include <cuda_runtime.h>
#include <math.h>

// Problem constants
#define BB   32
#define LL   2048
#define DIN  64
#define NC   32
#define DC   16
#define OUTD 512           // NC*DC
#define EPSQ 1e-7f

#define K1_CHUNKS 16
#define K3_CHUNKS 8        // blocks per batch in routing pass (256 l's each)
#define K3_WARPS  4
#define K3_LPW    64       // l's per warp

// Scratch (static device allocations only — no cudaMalloc allowed)
__device__ float g_colsum_part[BB][K1_CHUNKS][DIN];
__device__ float g_s_part[BB][K3_CHUNKS][NC][DIN];   // 2 MB
__device__ float g_v[BB][NC][DIN];

// ---------------------------------------------------------------------------
// K0: no-op padding so ncu's "-s 5 -c 1" lands on k3_route (launch index 5).
// ---------------------------------------------------------------------------
__global__ void k0_noop() {}

// ---------------------------------------------------------------------------
// K1: column sums  colsum_part[b][chunk][i] = sum over 128 l's of u[b,l,i]
// grid (K1_CHUNKS, BB), 256 threads   (exact R7 form)
// ---------------------------------------------------------------------------
__global__ void k1_colsum(const float* __restrict__ u) {
    const int b = blockIdx.y, chunk = blockIdx.x;
    const int tid = threadIdx.x;
    const int col4 = tid & 15;
    const int g    = tid >> 4;

    const float4* up = (const float4*)(u + ((size_t)b * LL + (size_t)chunk * 128) * DIN);
    float4 acc = make_float4(0.f, 0.f, 0.f, 0.f);
    #pragma unroll
    for (int r = 0; r < 8; r++) {
        float4 x = up[(size_t)(g + r * 16) * 16 + col4];
        acc.x += x.x; acc.y += x.y; acc.z += x.z; acc.w += x.w;
    }
    __shared__ __align__(16) float4 red[16][16];
    red[g][col4] = acc;
    __syncthreads();
    if (tid < 16) {
        float4 s = red[0][tid];
        #pragma unroll
        for (int i = 1; i < 16; i++) {
            float4 x = red[i][tid];
            s.x += x.x; s.y += x.y; s.z += x.z; s.w += x.w;
        }
        ((float4*)g_colsum_part[b][chunk])[tid] = s;
    }
}

// ---------------------------------------------------------------------------
// K2: per-(b,n) epilogue. grid (NC, BB), 64 threads   (exact R7 form)
// ---------------------------------------------------------------------------
__global__ void __launch_bounds__(64, 16) k2_update(const float* __restrict__ W,
                                                    float* __restrict__ out_final,
                                                    int mode) {
    const int n = blockIdx.x, b = blockIdx.y;
    const int t = threadIdx.x;        // 0..63 == element index i

    __shared__ float s_sm[DIN];
    __shared__ float out_sm[DC];

    float a = 0.f;
    if (mode == 0) {
        #pragma unroll
        for (int c = 0; c < K1_CHUNKS; c++)
            a += g_colsum_part[b][c][t];
        a *= (1.0f / 32.0f);
    } else {
        #pragma unroll
        for (int c = 0; c < K3_CHUNKS; c++)
            a += g_s_part[b][c][n][t];
    }
    s_sm[t] = a;
    __syncthreads();

    if (t < 32) {
        float raw = 0.f;
        if (t < DC) {
            const float* Wc = W + (size_t)n * DC + t;   // W[i*512 + n*16 + t]
            #pragma unroll
            for (int i = 0; i < DIN; i++)
                raw = fmaf(s_sm[i], Wc[(size_t)i * OUTD], raw);
        }
        float s2 = raw * raw;
        #pragma unroll
        for (int off = 8; off; off >>= 1)
            s2 += __shfl_xor_sync(0xffffffffu, s2, off, 16);
        float o = raw * rsqrtf(s2 + EPSQ);
        if (t < DC) {
            if (mode == 2) out_final[(size_t)b * OUTD + (size_t)n * DC + t] = o;
            else           out_sm[t] = o;
        }
    }

    if (mode != 2) {
        __syncthreads();
        const float* Wr = W + (size_t)t * OUTD + (size_t)n * DC;
        float v = 0.f;
        #pragma unroll
        for (int d = 0; d < DC; d++)
            v = fmaf(Wr[d], out_sm[d], v);
        g_v[b][n][t] = v;
    }
}

// ---------------------------------------------------------------------------
// K3: fused routing pass, R7 form + register double-buffered u-row prefetch.
// Iteration j stores rows j/j+1 to smem, then IMMEDIATELY issues LDGs for
// rows j+2/j+3 so they retire under the 256-FMA compute body.
// Per (b,l): logits[n] = u[l,:].v[n,:]; c = softmax_n; s[n,:] += c*u[l,:]
// grid (K3_CHUNKS, BB), 128 threads (4 warps).
// ---------------------------------------------------------------------------
__global__ void __launch_bounds__(128, 1) k3_route(const float* __restrict__ u) {
    const int b = blockIdx.y, chunk = blockIdx.x;
    const int w = threadIdx.x >> 5;
    const int lane = threadIdx.x & 31;       // lane == capsule index n

    __shared__ __align__(16) float u_buf[K3_WARPS][2][64];
    __shared__ __align__(16) float s_blk[K3_WARPS][NC][65];   // padded

    float4 v4[16];
    const float4* vp = (const float4*)(&g_v[b][lane][0]);
    #pragma unroll
    for (int k = 0; k < 16; k++) v4[k] = vp[k];

    float4 s4[16];
    #pragma unroll
    for (int k = 0; k < 16; k++) s4[k] = make_float4(0.f, 0.f, 0.f, 0.f);

    const int l0 = chunk * (K3_WARPS * K3_LPW) + w * K3_LPW;
    const float* ub = u + ((size_t)b * LL + l0) * DIN;

    // preload rows 0,1
    float2 ra = ((const float2*)(ub))[lane];
    float2 rb = ((const float2*)(ub + DIN))[lane];

    for (int j = 0; j < K3_LPW; j += 2) {
        __syncwarp();                         // WAR vs previous iteration's reads
        ((float2*)u_buf[w][0])[lane] = ra;
        ((float2*)u_buf[w][1])[lane] = rb;

        // prefetch next pair (issued before the compute body; retires under it)
        float2 na, nb;
        if (j + 2 < K3_LPW) {
            na = ((const float2*)(ub + (size_t)(j + 2) * DIN))[lane];
            nb = ((const float2*)(ub + (size_t)(j + 3) * DIN))[lane];
        } else {
            na = make_float2(0.f, 0.f);
            nb = make_float2(0.f, 0.f);
        }
        __syncwarp();
        const float4* uA = (const float4*)u_buf[w][0];
        const float4* uB = (const float4*)u_buf[w][1];

        float lA0 = 0.f, lA1 = 0.f, lB0 = 0.f, lB1 = 0.f;
        #pragma unroll
        for (int k = 0; k < 16; k += 2) {
            float4 xA = uA[k], yA = uA[k + 1];
            float4 xB = uB[k], yB = uB[k + 1];
            lA0 = fmaf(xA.x, v4[k].x, lA0);     lA0 = fmaf(xA.y, v4[k].y, lA0);
            lA0 = fmaf(xA.z, v4[k].z, lA0);     lA0 = fmaf(xA.w, v4[k].w, lA0);
            lA1 = fmaf(yA.x, v4[k + 1].x, lA1); lA1 = fmaf(yA.y, v4[k + 1].y, lA1);
            lA1 = fmaf(yA.z, v4[k + 1].z, lA1); lA1 = fmaf(yA.w, v4[k + 1].w, lA1);
            lB0 = fmaf(xB.x, v4[k].x, lB0);     lB0 = fmaf(xB.y, v4[k].y, lB0);
            lB0 = fmaf(xB.z, v4[k].z, lB0);     lB0 = fmaf(xB.w, v4[k].w, lB0);
            lB1 = fmaf(yB.x, v4[k + 1].x, lB1); lB1 = fmaf(yB.y, v4[k + 1].y, lB1);
            lB1 = fmaf(yB.z, v4[k + 1].z, lB1); lB1 = fmaf(yB.w, v4[k + 1].w, lB1);
        }
        float eA = __expf(lA0 + lA1);
        float eB = __expf(lB0 + lB1);
        float sA = eA, sB = eB;
        #pragma unroll
        for (int off = 16; off; off >>= 1) {
            sA += __shfl_xor_sync(0xffffffffu, sA, off);
            sB += __shfl_xor_sync(0xffffffffu, sB, off);
        }
        float cA = __fdividef(eA, sA);
        float cB = __fdividef(eB, sB);

        #pragma unroll
        for (int k = 0; k < 16; k++) {
            float4 xA = uA[k], xB = uB[k];
            s4[k].x = fmaf(cA, xA.x, fmaf(cB, xB.x, s4[k].x));
            s4[k].y = fmaf(cA, xA.y, fmaf(cB, xB.y, s4[k].y));
            s4[k].z = fmaf(cA, xA.z, fmaf(cB, xB.z, s4[k].z));
            s4[k].w = fmaf(cA, xA.w, fmaf(cB, xB.w, s4[k].w));
        }

        ra = na; rb = nb;
    }

    #pragma unroll
    for (int k = 0; k < 16; k++) {
        s_blk[w][lane][4 * k + 0] = s4[k].x;
        s_blk[w][lane][4 * k + 1] = s4[k].y;
        s_blk[w][lane][4 * k + 2] = s4[k].z;
        s_blk[w][lane][4 * k + 3] = s4[k].w;
    }
    __syncthreads();

    float* outp = (float*)g_s_part[b][chunk];
    for (int e = threadIdx.x; e < NC * DIN; e += 128) {
        int n = e >> 6, i = e & 63;
        outp[e] = s_blk[0][n][i] + s_blk[1][n][i] + s_blk[2][n][i] + s_blk[3][n][i];
    }
}

// ---------------------------------------------------------------------------
extern "C" void kernel_launch(void* const* d_in, const int* in_sizes, int n_in,
                              void* d_out, int out_size) {
    const float* u = (const float*)d_in[0];   // [32, 2048, 64]
    const float* W = (const float*)d_in[1];   // [1, 64, 512]
    float* out = (float*)d_out;               // [32, 32, 16]

    // padding so ncu (-s 5 -c 1) profiles k3_route at launch index 5
    k0_noop<<<1, 32>>>();
    k0_noop<<<1, 32>>>();
    k0_noop<<<1, 32>>>();

    // iteration 0: uniform c -> colsum path
    k1_colsum<<<dim3(K1_CHUNKS, BB), 256>>>(u);
    k2_update<<<dim3(NC, BB), 64>>>(W, out, 0);   // outputs0 + v0
    // iteration 1  (launch index 5 -> ncu target)
    k3_route<<<dim3(K3_CHUNKS, BB), 128>>>(u);
    k2_update<<<dim3(NC, BB), 64>>>(W, out, 1);   // outputs1 + v1
    // iteration 2 (final)
    k3_route<<<dim3(K3_CHUNKS, BB), 128>>>(u);
    k2_update<<<dim3(NC, BB), 64>>>(W, out, 2);   // outputs2 -> d_out
}

// round 17
// speedup vs baseline: 1.0713x; 1.0199x over previous
#include <cuda_runtime.h>
#include <math.h>

// Problem constants
#define BB   32
#define LL   2048
#define DIN  64
#define NC   32
#define DC   16
#define OUTD 512           // NC*DC
#define EPSQ 1e-7f

#define K1_CHUNKS 32       // 64 rows per chunk -> 1024 CTAs, 2x concurrency
#define K3_CHUNKS 8        // blocks per batch in routing pass (256 l's each)
#define K3_WARPS  4
#define K3_LPW    64       // l's per warp

// Scratch (static device allocations only — no cudaMalloc allowed)
__device__ float g_colsum_part[BB][K1_CHUNKS][DIN];
__device__ float g_s_part[BB][K3_CHUNKS][NC][DIN];   // 2 MB
__device__ float g_v[BB][NC][DIN];

// ---------------------------------------------------------------------------
// K1: column sums  colsum_part[b][chunk][i] = sum over 64 l's of u[b,l,i]
// grid (K1_CHUNKS, BB), 256 threads, 4 float4 loads per thread
// ---------------------------------------------------------------------------
__global__ void k1_colsum(const float* __restrict__ u) {
    const int b = blockIdx.y, chunk = blockIdx.x;
    const int tid = threadIdx.x;
    const int col4 = tid & 15;   // float4 column 0..15
    const int g    = tid >> 4;   // row group 0..15

    const float4* up = (const float4*)(u + ((size_t)b * LL + (size_t)chunk * 64) * DIN);
    float4 acc = make_float4(0.f, 0.f, 0.f, 0.f);
    #pragma unroll
    for (int r = 0; r < 4; r++) {
        float4 x = up[(size_t)(g + r * 16) * 16 + col4];
        acc.x += x.x; acc.y += x.y; acc.z += x.z; acc.w += x.w;
    }
    __shared__ __align__(16) float4 red[16][16];
    red[g][col4] = acc;
    __syncthreads();
    if (tid < 16) {
        float4 s = red[0][tid];
        #pragma unroll
        for (int i = 1; i < 16; i++) {
            float4 x = red[i][tid];
            s.x += x.x; s.y += x.y; s.z += x.z; s.w += x.w;
        }
        ((float4*)g_colsum_part[b][chunk])[tid] = s;
    }
}

// ---------------------------------------------------------------------------
// K2: per-(b,n) epilogue. grid (NC, BB), 64 threads   (R7 form)
// ---------------------------------------------------------------------------
__global__ void __launch_bounds__(64, 16) k2_update(const float* __restrict__ W,
                                                    float* __restrict__ out_final,
                                                    int mode) {
    const int n = blockIdx.x, b = blockIdx.y;
    const int t = threadIdx.x;        // 0..63 == element index i

    __shared__ float s_sm[DIN];
    __shared__ float out_sm[DC];

    float a = 0.f;
    if (mode == 0) {
        #pragma unroll
        for (int c = 0; c < K1_CHUNKS; c++)
            a += g_colsum_part[b][c][t];
        a *= (1.0f / 32.0f);
    } else {
        #pragma unroll
        for (int c = 0; c < K3_CHUNKS; c++)
            a += g_s_part[b][c][n][t];
    }
    s_sm[t] = a;
    __syncthreads();

    if (t < 32) {
        float raw = 0.f;
        if (t < DC) {
            const float* Wc = W + (size_t)n * DC + t;   // W[i*512 + n*16 + t]
            #pragma unroll
            for (int i = 0; i < DIN; i++)
                raw = fmaf(s_sm[i], Wc[(size_t)i * OUTD], raw);
        }
        float s2 = raw * raw;
        #pragma unroll
        for (int off = 8; off; off >>= 1)
            s2 += __shfl_xor_sync(0xffffffffu, s2, off, 16);
        float o = raw * rsqrtf(s2 + EPSQ);
        if (t < DC) {
            if (mode == 2) out_final[(size_t)b * OUTD + (size_t)n * DC + t] = o;
            else           out_sm[t] = o;
        }
    }

    if (mode != 2) {
        __syncthreads();
        const float* Wr = W + (size_t)t * OUTD + (size_t)n * DC;
        float v = 0.f;
        #pragma unroll
        for (int d = 0; d < DC; d++)
            v = fmaf(Wr[d], out_sm[d], v);
        g_v[b][n][t] = v;
    }
}

// ---------------------------------------------------------------------------
// K3: fused routing pass, depth-2 register prefetch (two row-pairs in flight
// -> LDG latency ~577cyc covered by ~2 compute bodies).
// Per (b,l): logits[n] = u[l,:].v[n,:]; c = softmax_n; s[n,:] += c*u[l,:]
// grid (K3_CHUNKS, BB), 128 threads (4 warps).
// ---------------------------------------------------------------------------
__global__ void __launch_bounds__(128, 1) k3_route(const float* __restrict__ u) {
    const int b = blockIdx.y, chunk = blockIdx.x;
    const int w = threadIdx.x >> 5;
    const int lane = threadIdx.x & 31;       // lane == capsule index n

    __shared__ __align__(16) float u_buf[K3_WARPS][2][64];
    __shared__ __align__(16) float s_blk[K3_WARPS][NC][65];   // padded

    float4 v4[16];
    const float4* vp = (const float4*)(&g_v[b][lane][0]);
    #pragma unroll
    for (int k = 0; k < 16; k++) v4[k] = vp[k];

    float4 s4[16];
    #pragma unroll
    for (int k = 0; k < 16; k++) s4[k] = make_float4(0.f, 0.f, 0.f, 0.f);

    const int l0 = chunk * (K3_WARPS * K3_LPW) + w * K3_LPW;
    const float* ub = u + ((size_t)b * LL + l0) * DIN;

    // preload pairs for iterations j=0 and j=2
    float2 p0a = ((const float2*)(ub + 0 * DIN))[lane];
    float2 p0b = ((const float2*)(ub + 1 * DIN))[lane];
    float2 p1a = ((const float2*)(ub + 2 * DIN))[lane];
    float2 p1b = ((const float2*)(ub + 3 * DIN))[lane];

    for (int j = 0; j < K3_LPW; j += 2) {
        __syncwarp();                         // WAR vs previous iteration's reads
        ((float2*)u_buf[w][0])[lane] = p0a;
        ((float2*)u_buf[w][1])[lane] = p0b;

        // prefetch pair for iteration j+4 (distance 2 -> ~2 bodies of cover)
        float2 na, nb;
        if (j + 4 < K3_LPW) {
            na = ((const float2*)(ub + (size_t)(j + 4) * DIN))[lane];
            nb = ((const float2*)(ub + (size_t)(j + 5) * DIN))[lane];
        } else {
            na = make_float2(0.f, 0.f);
            nb = make_float2(0.f, 0.f);
        }
        __syncwarp();
        const float4* uA = (const float4*)u_buf[w][0];
        const float4* uB = (const float4*)u_buf[w][1];

        float lA0 = 0.f, lA1 = 0.f, lB0 = 0.f, lB1 = 0.f;
        #pragma unroll
        for (int k = 0; k < 16; k += 2) {
            float4 xA = uA[k], yA = uA[k + 1];
            float4 xB = uB[k], yB = uB[k + 1];
            lA0 = fmaf(xA.x, v4[k].x, lA0);     lA0 = fmaf(xA.y, v4[k].y, lA0);
            lA0 = fmaf(xA.z, v4[k].z, lA0);     lA0 = fmaf(xA.w, v4[k].w, lA0);
            lA1 = fmaf(yA.x, v4[k + 1].x, lA1); lA1 = fmaf(yA.y, v4[k + 1].y, lA1);
            lA1 = fmaf(yA.z, v4[k + 1].z, lA1); lA1 = fmaf(yA.w, v4[k + 1].w, lA1);
            lB0 = fmaf(xB.x, v4[k].x, lB0);     lB0 = fmaf(xB.y, v4[k].y, lB0);
            lB0 = fmaf(xB.z, v4[k].z, lB0);     lB0 = fmaf(xB.w, v4[k].w, lB0);
            lB1 = fmaf(yB.x, v4[k + 1].x, lB1); lB1 = fmaf(yB.y, v4[k + 1].y, lB1);
            lB1 = fmaf(yB.z, v4[k + 1].z, lB1); lB1 = fmaf(yB.w, v4[k + 1].w, lB1);
        }
        float eA = __expf(lA0 + lA1);
        float eB = __expf(lB0 + lB1);
        float sA = eA, sB = eB;
        #pragma unroll
        for (int off = 16; off; off >>= 1) {
            sA += __shfl_xor_sync(0xffffffffu, sA, off);
            sB += __shfl_xor_sync(0xffffffffu, sB, off);
        }
        float cA = __fdividef(eA, sA);
        float cB = __fdividef(eB, sB);

        #pragma unroll
        for (int k = 0; k < 16; k++) {
            float4 xA = uA[k], xB = uB[k];
            s4[k].x = fmaf(cA, xA.x, fmaf(cB, xB.x, s4[k].x));
            s4[k].y = fmaf(cA, xA.y, fmaf(cB, xB.y, s4[k].y));
            s4[k].z = fmaf(cA, xA.z, fmaf(cB, xB.z, s4[k].z));
            s4[k].w = fmaf(cA, xA.w, fmaf(cB, xB.w, s4[k].w));
        }

        // rotate prefetch pipeline
        p0a = p1a; p0b = p1b;
        p1a = na;  p1b = nb;
    }

    #pragma unroll
    for (int k = 0; k < 16; k++) {
        s_blk[w][lane][4 * k + 0] = s4[k].x;
        s_blk[w][lane][4 * k + 1] = s4[k].y;
        s_blk[w][lane][4 * k + 2] = s4[k].z;
        s_blk[w][lane][4 * k + 3] = s4[k].w;
    }
    __syncthreads();

    float* outp = (float*)g_s_part[b][chunk];
    for (int e = threadIdx.x; e < NC * DIN; e += 128) {
        int n = e >> 6, i = e & 63;
        outp[e] = s_blk[0][n][i] + s_blk[1][n][i] + s_blk[2][n][i] + s_blk[3][n][i];
    }
}

// ---------------------------------------------------------------------------
extern "C" void kernel_launch(void* const* d_in, const int* in_sizes, int n_in,
                              void* d_out, int out_size) {
    const float* u = (const float*)d_in[0];   // [32, 2048, 64]
    const float* W = (const float*)d_in[1];   // [1, 64, 512]
    float* out = (float*)d_out;               // [32, 32, 16]

    // iteration 0: uniform c -> colsum path
    k1_colsum<<<dim3(K1_CHUNKS, BB), 256>>>(u);
    k2_update<<<dim3(NC, BB), 64>>>(W, out, 0);   // outputs0 + v0
    // iteration 1
    k3_route<<<dim3(K3_CHUNKS, BB), 128>>>(u);
    k2_update<<<dim3(NC, BB), 64>>>(W, out, 1);   // outputs1 + v1
    // iteration 2 (final)
    k3_route<<<dim3(K3_CHUNKS, BB), 128>>>(u);
    k2_update<<<dim3(NC, BB), 64>>>(W, out, 2);   // outputs2 -> d_out
}